// round 5
// baseline (speedup 1.0000x reference)
#include <cuda_runtime.h>
#include <cuda_bf16.h>
#include <cstdint>

#define BATCH 32768
#define HDIM  512
#define MD    8
#define CDIM  1024
#define NCAT  262144
#define KDIM  532
#define KP    544            // K padded to 17*32
#define NKIT  17
#define EPS   1e-6f

// ---------------- static scratch ----------------
__device__ float g_sums[BATCH * MD];
__device__ float g_counts[BATCH];
__device__ float g_meta[BATCH * 20];
__device__ float g_bias6[BATCH * 6];
__device__ int8_t g_xh[(size_t)BATCH * KP];    // 17.8 MB
__device__ int8_t g_xl[(size_t)BATCH * KP];    // 17.8 MB
__device__ int8_t g_wh[CDIM * KP];
__device__ int8_t g_wl[CDIM * KP];
__device__ float g_feat[(size_t)BATCH * CDIM]; // 128 MB

// ---------------- helpers ----------------
__device__ __forceinline__ float warp_sum(float v) {
#pragma unroll
    for (int o = 16; o > 0; o >>= 1) v += __shfl_xor_sync(0xffffffffu, v, o);
    return v;
}
__device__ __forceinline__ uint32_t smem_u32(const void* p) {
    uint32_t a;
    asm("{ .reg .u64 t; cvta.to.shared.u64 t, %1; cvt.u32.u64 %0, t; }" : "=r"(a) : "l"(p));
    return a;
}
__device__ __forceinline__ void cp16(uint32_t dst, const void* src) {
    unsigned long long g = (unsigned long long)__cvta_generic_to_global(src);
    asm volatile("cp.async.cg.shared.global [%0], [%1], 16;" :: "r"(dst), "l"(g) : "memory");
}
__device__ __forceinline__ void cp_commit() {
    asm volatile("cp.async.commit_group;" ::: "memory");
}
template <int N>
__device__ __forceinline__ void cp_wait() {
    asm volatile("cp.async.wait_group %0;" :: "n"(N) : "memory");
}
__device__ __forceinline__ void ldsm4(uint32_t* r, uint32_t addr) {
    asm volatile("ldmatrix.sync.aligned.m8n8.x4.shared.b16 {%0,%1,%2,%3}, [%4];"
                 : "=r"(r[0]), "=r"(r[1]), "=r"(r[2]), "=r"(r[3]) : "r"(addr));
}
__device__ __forceinline__ void imma16832(int* d, const uint32_t* a, const uint32_t* b) {
    asm volatile(
        "mma.sync.aligned.m16n8k32.row.col.s32.s8.s8.s32 "
        "{%0,%1,%2,%3}, {%4,%5,%6,%7}, {%8,%9}, {%0,%1,%2,%3};"
        : "+r"(d[0]), "+r"(d[1]), "+r"(d[2]), "+r"(d[3])
        : "r"(a[0]), "r"(a[1]), "r"(a[2]), "r"(a[3]), "r"(b[0]), "r"(b[1]));
}
// 15-bit fixed-point split: q in [-16384, 16319], q = 128*h + l, h in [-128,127], l in [-64,63]
__device__ __forceinline__ void quant_split(float x, float scale, int8_t& h, int8_t& l) {
    int q = __float2int_rn(x * scale);
    q = max(-16384, min(16319, q));
    int hi = (q + 64) >> 7;
    h = (int8_t)hi;
    l = (int8_t)(q - (hi << 7));
}

// ---------------- K0: zero segment scratch ----------------
__global__ void zero_kernel() {
    int i = blockIdx.x * blockDim.x + threadIdx.x;
    if (i < BATCH * MD) g_sums[i] = 0.0f;
    if (i < BATCH) g_counts[i] = 0.0f;
}

// ---------------- K1: ragged segment sum ----------------
__global__ void seg_kernel(const float* __restrict__ meta_table,
                           const int* __restrict__ cat_ids,
                           const int* __restrict__ cat_seg) {
    int i = blockIdx.x * blockDim.x + threadIdx.x;
    if (i >= NCAT) return;
    int c = cat_ids[i];
    int s = cat_seg[i];
    const float* e = meta_table + (size_t)c * MD;
#pragma unroll
    for (int d = 0; d < MD; d++) atomicAdd(&g_sums[s * MD + d], e[d]);
    atomicAdd(&g_counts[s], 1.0f);
}

// ---------------- K2: conv/relu/maxpool + credit biases ----------------
__global__ void meta_kernel(const float* __restrict__ meta_table,
                            const float* __restrict__ conv_w,
                            const float* __restrict__ conv_b,
                            const int* __restrict__ meta_ids,
                            const float* __restrict__ credit) {
    int b = blockIdx.x * blockDim.x + threadIdx.x;
    if (b >= BATCH) return;

    float mat[6][MD];
    float cnt = fmaxf(g_counts[b], 1.0f);
#pragma unroll
    for (int d = 0; d < MD; d++) mat[0][d] = g_sums[b * MD + d] / cnt;
#pragma unroll
    for (int r = 0; r < 5; r++) {
        int id = meta_ids[b * 5 + r];
        const float* e = meta_table + (size_t)id * MD;
#pragma unroll
        for (int d = 0; d < MD; d++) mat[r + 1][d] = e[d];
    }
    float conv[5][6];
#pragma unroll
    for (int o = 0; o < 5; o++) {
#pragma unroll
        for (int t = 0; t < 6; t++) {
            float a = conv_b[o];
#pragma unroll
            for (int i = 0; i < 6; i++)
#pragma unroll
                for (int k = 0; k < 3; k++)
                    a += mat[i][t + k] * conv_w[o * 18 + i * 3 + k];
            conv[o][t] = fmaxf(a, 0.0f);
        }
    }
#pragma unroll
    for (int o = 0; o < 5; o++)
#pragma unroll
        for (int t = 0; t < 4; t++)
            g_meta[b * 20 + o * 4 + t] =
                fmaxf(fmaxf(conv[o][t], conv[o][t + 1]), conv[o][t + 2]);

    float cv[6], s = 0.0f;
#pragma unroll
    for (int c = 0; c < 6; c++) { cv[c] = credit[b * 6 + c]; s += cv[c]; }
#pragma unroll
    for (int c = 0; c < 6; c++)
        g_bias6[b * 6 + c] = (s > 0.0f) ? cv[c] / s : (1.0f / 6.0f);
}

// ---------------- K3: LN1 -> int8 hi/lo fixed point (scale 2^11) ----------------
__global__ __launch_bounds__(256) void ln1_kernel(const float* __restrict__ encode,
                                                  const float* __restrict__ g1,
                                                  const float* __restrict__ b1) {
    int warp = threadIdx.x >> 5;
    int lane = threadIdx.x & 31;
    int row = blockIdx.x * 8 + warp;

    float v[17];
#pragma unroll
    for (int k = 0; k < 17; k++) {
        int j = k * 32 + lane;
        float x = 0.0f;
        if (j < HDIM)      x = encode[(size_t)row * HDIM + j];
        else if (j < KDIM) x = g_meta[row * 20 + (j - HDIM)];
        v[k] = x;
    }
    float s = 0.0f;
#pragma unroll
    for (int k = 0; k < 17; k++) s += v[k];
    s = warp_sum(s);
    float mu = s * (1.0f / KDIM);
    float sq = 0.0f;
#pragma unroll
    for (int k = 0; k < 17; k++) {
        int j = k * 32 + lane;
        float d = (j < KDIM) ? (v[k] - mu) : 0.0f;
        sq += d * d;
    }
    sq = warp_sum(sq);
    float rs = rsqrtf(sq * (1.0f / KDIM) + EPS);

    int8_t* dh = g_xh + (size_t)row * KP;
    int8_t* dl = g_xl + (size_t)row * KP;
#pragma unroll
    for (int k = 0; k < 17; k++) {
        int j = k * 32 + lane;
        float y = (j < KDIM) ? (g1[j] * (v[k] - mu) * rs + b1[j]) : 0.0f;
        int8_t h, l;
        quant_split(y, 2048.0f, h, l);
        dh[j] = h;
        dl[j] = l;
    }
}

// ---------------- K4: W1 -> int8 hi/lo (scale 2^15) ----------------
__global__ void wquant_kernel(const float* __restrict__ w) {
    int idx = blockIdx.x * blockDim.x + threadIdx.x;
    if (idx >= CDIM * KP) return;
    int n = idx / KP;
    int k = idx - n * KP;
    float v = (k < KDIM) ? w[(size_t)n * KDIM + k] : 0.0f;
    int8_t h, l;
    quant_split(v, 32768.0f, h, l);
    g_wh[idx] = h;
    g_wl[idx] = l;
}

// ---------------- K5: int8 4-term exact GEMM  feat = relu(x @ W^T + b) ----------------
// CTA 128x128, warp 32x64 (4 M-warps x 2 N-warps), K chunk 32, 4-stage cp.async.
// SMEM row: [32B hi | 32B lo | 16B pad] = 80B (20 words -> conflict-free ldsm).
#define ROW_B   80
#define A_STG   (128 * ROW_B)              // 10240
#define B_STG   (128 * ROW_B)              // 10240
#define STG     (A_STG + B_STG)            // 20480
#define NSTAGE  4
#define SMEM_TOT (NSTAGE * STG)            // 81920

__global__ __launch_bounds__(256, 1) void gemm1_imma(const float* __restrict__ bias) {
    extern __shared__ char sm[];
    int tid = threadIdx.x;
    int lane = tid & 31;
    int w = tid >> 5;
    int wm = (w & 3) * 32;      // warp M origin (4 warps over 128 rows)
    int wn = (w >> 2) * 64;     // warp N origin (2 warps over 128 cols)

    int m0 = blockIdx.y * 128;
    int n0 = blockIdx.x * 128;

    uint32_t sbase = smem_u32(sm);

    int acc_hh[2][8][4], acc_mid[2][8][4], acc_ll[2][8][4];
#pragma unroll
    for (int i = 0; i < 2; i++)
#pragma unroll
        for (int j = 0; j < 8; j++)
#pragma unroll
            for (int q = 0; q < 4; q++) {
                acc_hh[i][j][q] = 0; acc_mid[i][j][q] = 0; acc_ll[i][j][q] = 0;
            }

    auto load_stage = [&](int st, int kc) {
        uint32_t sa = sbase + st * STG;
        uint32_t sb = sa + A_STG;
        int ko = kc * 32;
#pragma unroll
        for (int i = 0; i < 2; i++) {
            int idx = i * 256 + tid;
            int row = idx >> 2, part = idx & 3;
            uint32_t dst = sa + row * ROW_B + ((part & 1) ? 16 : 0) + ((part >> 1) ? 32 : 0);
            const int8_t* src = ((part >> 1) ? g_xl : g_xh)
                                + (size_t)(m0 + row) * KP + ko + (part & 1) * 16;
            cp16(dst, src);
        }
#pragma unroll
        for (int i = 0; i < 2; i++) {
            int idx = i * 256 + tid;
            int row = idx >> 2, part = idx & 3;
            uint32_t dst = sb + row * ROW_B + ((part & 1) ? 16 : 0) + ((part >> 1) ? 32 : 0);
            const int8_t* src = ((part >> 1) ? g_wl : g_wh)
                                + (size_t)(n0 + row) * KP + ko + (part & 1) * 16;
            cp16(dst, src);
        }
        cp_commit();
    };

    load_stage(0, 0);
    load_stage(1, 1);
    load_stage(2, 2);

    int lrow = lane & 15;              // row within 16-row tile
    int koff = (lane >> 4) * 16;       // 0 or 16 (k bytes 0-15 vs 16-31)

    for (int kc = 0; kc < NKIT; kc++) {
        if (kc + 3 < NKIT) { load_stage((kc + 3) & 3, kc + 3); cp_wait<3>(); }
        else if (kc + 2 < NKIT) cp_wait<2>();
        else if (kc + 1 < NKIT) cp_wait<1>();
        else cp_wait<0>();
        __syncthreads();

        uint32_t sa = sbase + (kc & 3) * STG;
        uint32_t sb = sa + A_STG;

        uint32_t ah[2][4], al[2][4];
#pragma unroll
        for (int i = 0; i < 2; i++) {
            uint32_t base = sa + (wm + i * 16 + lrow) * ROW_B + koff;
            ldsm4(ah[i], base);
            ldsm4(al[i], base + 32);
        }

#pragma unroll
        for (int jj = 0; jj < 4; jj++) {
            uint32_t bh[4], bl[4];
            uint32_t bbase = sb + (wn + jj * 16 + lrow) * ROW_B + koff;
            ldsm4(bh, bbase);
            ldsm4(bl, bbase + 32);
            uint32_t bhe[2] = {bh[0], bh[2]}, bho[2] = {bh[1], bh[3]};
            uint32_t ble[2] = {bl[0], bl[2]}, blo[2] = {bl[1], bl[3]};
            int je = jj * 2, jo = jj * 2 + 1;
#pragma unroll
            for (int i = 0; i < 2; i++) {
                imma16832(acc_hh[i][je], ah[i], bhe);
                imma16832(acc_mid[i][je], ah[i], ble);
                imma16832(acc_mid[i][je], al[i], bhe);
                imma16832(acc_ll[i][je], al[i], ble);
                imma16832(acc_hh[i][jo], ah[i], bho);
                imma16832(acc_mid[i][jo], ah[i], blo);
                imma16832(acc_mid[i][jo], al[i], bho);
                imma16832(acc_ll[i][jo], al[i], blo);
            }
        }
        __syncthreads();
    }

    // ---- epilogue: combine terms, bias + relu -> g_feat ----
    // C = 2^-26 * (16384*S_hh + 128*S_mid + S_ll)
    int r2 = lane >> 2, c2 = (lane & 3) * 2;
#pragma unroll
    for (int i = 0; i < 2; i++) {
        int row0 = m0 + wm + i * 16 + r2;
#pragma unroll
        for (int j = 0; j < 8; j++) {
            int col = n0 + wn + j * 8 + c2;
            float b0 = bias[col], b1 = bias[col + 1];
            float c0 = (float)acc_hh[i][j][0] * 0x1p-12f + (float)acc_mid[i][j][0] * 0x1p-19f
                     + (float)acc_ll[i][j][0] * 0x1p-26f + b0;
            float c1 = (float)acc_hh[i][j][1] * 0x1p-12f + (float)acc_mid[i][j][1] * 0x1p-19f
                     + (float)acc_ll[i][j][1] * 0x1p-26f + b1;
            float c2v = (float)acc_hh[i][j][2] * 0x1p-12f + (float)acc_mid[i][j][2] * 0x1p-19f
                      + (float)acc_ll[i][j][2] * 0x1p-26f + b0;
            float c3 = (float)acc_hh[i][j][3] * 0x1p-12f + (float)acc_mid[i][j][3] * 0x1p-19f
                     + (float)acc_ll[i][j][3] * 0x1p-26f + b1;
            float2 v0 = {fmaxf(c0, 0.0f), fmaxf(c1, 0.0f)};
            float2 v1 = {fmaxf(c2v, 0.0f), fmaxf(c3, 0.0f)};
            *(float2*)(g_feat + (size_t)row0 * CDIM + col) = v0;
            *(float2*)(g_feat + (size_t)(row0 + 8) * CDIM + col) = v1;
        }
    }
}

// ---------------- K6: LN2 + output GEMM (6 cols) + biases ----------------
__global__ __launch_bounds__(256) void out_kernel(const float* __restrict__ g2,
                                                  const float* __restrict__ b2,
                                                  const float* __restrict__ out_w,
                                                  const float* __restrict__ out_b,
                                                  float* __restrict__ out) {
    __shared__ float sw[6 * CDIM];
    for (int i = threadIdx.x; i < 6 * CDIM; i += 256) sw[i] = out_w[i];
    __syncthreads();

    int warp = threadIdx.x >> 5;
    int lane = threadIdx.x & 31;
    int row = blockIdx.x * 8 + warp;

    const float* f = g_feat + (size_t)row * CDIM;
    float v[32];
    float s = 0.0f;
#pragma unroll
    for (int k = 0; k < 32; k++) { v[k] = f[k * 32 + lane]; s += v[k]; }
    s = warp_sum(s);
    float mu = s * (1.0f / CDIM);
    float sq = 0.0f;
#pragma unroll
    for (int k = 0; k < 32; k++) { float d = v[k] - mu; sq += d * d; }
    sq = warp_sum(sq);
    float rs = rsqrtf(sq * (1.0f / CDIM) + EPS);

    float acc[6] = {0, 0, 0, 0, 0, 0};
#pragma unroll
    for (int k = 0; k < 32; k++) {
        int j = k * 32 + lane;
        float y = g2[j] * (v[k] - mu) * rs + b2[j];
#pragma unroll
        for (int c = 0; c < 6; c++) acc[c] += y * sw[c * CDIM + j];
    }
#pragma unroll
    for (int c = 0; c < 6; c++) acc[c] = warp_sum(acc[c]);

    if (lane == 0) {
#pragma unroll
        for (int c = 0; c < 6; c++)
            out[row * 6 + c] = acc[c] + out_b[c] + g_bias6[row * 6 + c];
    }
}

// ---------------- launch ----------------
extern "C" void kernel_launch(void* const* d_in, const int* in_sizes, int n_in,
                              void* d_out, int out_size) {
    const float* encode     = (const float*)d_in[0];
    const float* credit_vec = (const float*)d_in[1];
    const float* meta_table = (const float*)d_in[2];
    const float* conv_w     = (const float*)d_in[3];
    const float* conv_b     = (const float*)d_in[4];
    const float* ln1_g      = (const float*)d_in[5];
    const float* ln1_b      = (const float*)d_in[6];
    const float* mlp1_w     = (const float*)d_in[7];
    const float* mlp1_b     = (const float*)d_in[8];
    const float* ln2_g      = (const float*)d_in[9];
    const float* ln2_b      = (const float*)d_in[10];
    const float* out_w      = (const float*)d_in[11];
    const float* out_b      = (const float*)d_in[12];
    const int*   meta_ids   = (const int*)d_in[13];
    const int*   cat_ids    = (const int*)d_in[14];
    const int*   cat_seg    = (const int*)d_in[15];
    float* out = (float*)d_out;

    static bool init = false;
    if (!init) {
        cudaFuncSetAttribute(gemm1_imma, cudaFuncAttributeMaxDynamicSharedMemorySize, SMEM_TOT);
        init = true;
    }

    zero_kernel<<<(BATCH * MD + 255) / 256, 256>>>();
    seg_kernel<<<(NCAT + 255) / 256, 256>>>(meta_table, cat_ids, cat_seg);
    meta_kernel<<<(BATCH + 127) / 128, 128>>>(meta_table, conv_w, conv_b, meta_ids, credit_vec);
    ln1_kernel<<<BATCH / 8, 256>>>(encode, ln1_g, ln1_b);
    wquant_kernel<<<(CDIM * KP + 255) / 256, 256>>>(mlp1_w);
    {
        dim3 grid(CDIM / 128, BATCH / 128);   // (8, 256), N fastest -> A tiles L2-resident
        gemm1_imma<<<grid, 256, SMEM_TOT>>>(mlp1_b);
    }
    out_kernel<<<BATCH / 8, 256>>>(ln2_g, ln2_b, out_w, out_b, out);
}

// round 6
// speedup vs baseline: 3.5125x; 3.5125x over previous
#include <cuda_runtime.h>
#include <cuda_fp16.h>
#include <cstdint>

#define BATCH 32768
#define HDIM  512
#define MD    8
#define CDIM  1024
#define NCAT  262144
#define KDIM  532
#define KP    544            // K padded to 17*32
#define NKIT  17
#define EPS   1e-6f

// ---------------- static scratch ----------------
__device__ float g_sums[BATCH * MD];
__device__ float g_counts[BATCH];
__device__ float g_meta[BATCH * 20];
__device__ float g_bias6[BATCH * 6];
__device__ __half g_x[(size_t)BATCH * KP];     // 35.7 MB (single fp16)
__device__ __half g_wh[CDIM * KP];             // W hi
__device__ __half g_wl[CDIM * KP];             // W lo
__device__ float g_feat[(size_t)BATCH * CDIM]; // 128 MB

// ---------------- helpers ----------------
__device__ __forceinline__ float warp_sum(float v) {
#pragma unroll
    for (int o = 16; o > 0; o >>= 1) v += __shfl_xor_sync(0xffffffffu, v, o);
    return v;
}
__device__ __forceinline__ uint32_t smem_u32(const void* p) {
    uint32_t a;
    asm("{ .reg .u64 t; cvta.to.shared.u64 t, %1; cvt.u32.u64 %0, t; }" : "=r"(a) : "l"(p));
    return a;
}
__device__ __forceinline__ void cp16(uint32_t dst, const void* src) {
    unsigned long long g = (unsigned long long)__cvta_generic_to_global(src);
    asm volatile("cp.async.cg.shared.global [%0], [%1], 16;" :: "r"(dst), "l"(g) : "memory");
}
__device__ __forceinline__ void cp_commit() {
    asm volatile("cp.async.commit_group;" ::: "memory");
}
template <int N>
__device__ __forceinline__ void cp_wait() {
    asm volatile("cp.async.wait_group %0;" :: "n"(N) : "memory");
}
__device__ __forceinline__ void ldsm4(uint32_t* r, uint32_t addr) {
    asm volatile("ldmatrix.sync.aligned.m8n8.x4.shared.b16 {%0,%1,%2,%3}, [%4];"
                 : "=r"(r[0]), "=r"(r[1]), "=r"(r[2]), "=r"(r[3]) : "r"(addr));
}
__device__ __forceinline__ void mma16816(float* d, const uint32_t* a, const uint32_t* b) {
    asm volatile(
        "mma.sync.aligned.m16n8k16.row.col.f32.f16.f16.f32 "
        "{%0,%1,%2,%3}, {%4,%5,%6,%7}, {%8,%9}, {%0,%1,%2,%3};"
        : "+f"(d[0]), "+f"(d[1]), "+f"(d[2]), "+f"(d[3])
        : "r"(a[0]), "r"(a[1]), "r"(a[2]), "r"(a[3]), "r"(b[0]), "r"(b[1]));
}

// ---------------- K0: zero segment scratch ----------------
__global__ void zero_kernel() {
    int i = blockIdx.x * blockDim.x + threadIdx.x;
    if (i < BATCH * MD) g_sums[i] = 0.0f;
    if (i < BATCH) g_counts[i] = 0.0f;
}

// ---------------- K1: ragged segment sum ----------------
__global__ void seg_kernel(const float* __restrict__ meta_table,
                           const int* __restrict__ cat_ids,
                           const int* __restrict__ cat_seg) {
    int i = blockIdx.x * blockDim.x + threadIdx.x;
    if (i >= NCAT) return;
    int c = cat_ids[i];
    int s = cat_seg[i];
    const float* e = meta_table + (size_t)c * MD;
#pragma unroll
    for (int d = 0; d < MD; d++) atomicAdd(&g_sums[s * MD + d], e[d]);
    atomicAdd(&g_counts[s], 1.0f);
}

// ---------------- K2: conv/relu/maxpool + credit biases ----------------
__global__ void meta_kernel(const float* __restrict__ meta_table,
                            const float* __restrict__ conv_w,
                            const float* __restrict__ conv_b,
                            const int* __restrict__ meta_ids,
                            const float* __restrict__ credit) {
    int b = blockIdx.x * blockDim.x + threadIdx.x;
    if (b >= BATCH) return;

    float mat[6][MD];
    float cnt = fmaxf(g_counts[b], 1.0f);
#pragma unroll
    for (int d = 0; d < MD; d++) mat[0][d] = g_sums[b * MD + d] / cnt;
#pragma unroll
    for (int r = 0; r < 5; r++) {
        int id = meta_ids[b * 5 + r];
        const float* e = meta_table + (size_t)id * MD;
#pragma unroll
        for (int d = 0; d < MD; d++) mat[r + 1][d] = e[d];
    }
    float conv[5][6];
#pragma unroll
    for (int o = 0; o < 5; o++) {
#pragma unroll
        for (int t = 0; t < 6; t++) {
            float a = conv_b[o];
#pragma unroll
            for (int i = 0; i < 6; i++)
#pragma unroll
                for (int k = 0; k < 3; k++)
                    a += mat[i][t + k] * conv_w[o * 18 + i * 3 + k];
            conv[o][t] = fmaxf(a, 0.0f);
        }
    }
#pragma unroll
    for (int o = 0; o < 5; o++)
#pragma unroll
        for (int t = 0; t < 4; t++)
            g_meta[b * 20 + o * 4 + t] =
                fmaxf(fmaxf(conv[o][t], conv[o][t + 1]), conv[o][t + 2]);

    float cv[6], s = 0.0f;
#pragma unroll
    for (int c = 0; c < 6; c++) { cv[c] = credit[b * 6 + c]; s += cv[c]; }
#pragma unroll
    for (int c = 0; c < 6; c++)
        g_bias6[b * 6 + c] = (s > 0.0f) ? cv[c] / s : (1.0f / 6.0f);
}

// ---------------- K3: LN1 -> fp16 (single), K padded to 544 ----------------
__global__ __launch_bounds__(256) void ln1_kernel(const float* __restrict__ encode,
                                                  const float* __restrict__ g1,
                                                  const float* __restrict__ b1) {
    int warp = threadIdx.x >> 5;
    int lane = threadIdx.x & 31;
    int row = blockIdx.x * 8 + warp;

    float v[17];
#pragma unroll
    for (int k = 0; k < 17; k++) {
        int j = k * 32 + lane;
        float x = 0.0f;
        if (j < HDIM)      x = encode[(size_t)row * HDIM + j];
        else if (j < KDIM) x = g_meta[row * 20 + (j - HDIM)];
        v[k] = x;
    }
    float s = 0.0f;
#pragma unroll
    for (int k = 0; k < 17; k++) s += v[k];
    s = warp_sum(s);
    float mu = s * (1.0f / KDIM);
    float sq = 0.0f;
#pragma unroll
    for (int k = 0; k < 17; k++) {
        int j = k * 32 + lane;
        float d = (j < KDIM) ? (v[k] - mu) : 0.0f;
        sq += d * d;
    }
    sq = warp_sum(sq);
    float rs = rsqrtf(sq * (1.0f / KDIM) + EPS);

    __half* dx = g_x + (size_t)row * KP;
#pragma unroll
    for (int k = 0; k < 17; k++) {
        int j = k * 32 + lane;
        float y = (j < KDIM) ? (g1[j] * (v[k] - mu) * rs + b1[j]) : 0.0f;
        dx[j] = __float2half(y);
    }
}

// ---------------- K4: W1 -> fp16 hi/lo, padded ----------------
__global__ void wconv_kernel(const float* __restrict__ w) {
    int idx = blockIdx.x * blockDim.x + threadIdx.x;
    if (idx >= CDIM * KP) return;
    int n = idx / KP;
    int k = idx - n * KP;
    float v = (k < KDIM) ? w[(size_t)n * KDIM + k] : 0.0f;
    __half h = __float2half(v);
    __half l = __float2half(v - __half2float(h));
    g_wh[idx] = h;
    g_wl[idx] = l;
}

// ---------------- K5: fp16 2-term GEMM  feat = relu(x @ W^T + b) ----------------
// CTA 256x128, 512 threads (16 warps), warp tile 32x64, K chunk 32, 3-stage cp.async.
// A row: 64B x + 16B pad = 80B.  B row: 64B hi + 64B lo + 16B pad = 144B.
#define A_ROWS  256
#define B_ROWS  128
#define AROW_B  80
#define BROW_B  144
#define A_STG   (A_ROWS * AROW_B)          // 20480
#define B_STG   (B_ROWS * BROW_B)          // 18432
#define STG     (A_STG + B_STG)            // 38912
#define NSTAGE  3
#define SMEM_TOT (NSTAGE * STG)            // 116736

__global__ __launch_bounds__(512, 1) void gemm1_mma(const float* __restrict__ bias) {
    extern __shared__ char sm[];
    int tid = threadIdx.x;
    int lane = tid & 31;
    int w = tid >> 5;
    int wm = (w & 7) * 32;      // 8 M-warps
    int wn = (w >> 3) * 64;     // 2 N-warps

    int m0 = blockIdx.y * A_ROWS;
    int n0 = blockIdx.x * B_ROWS;

    uint32_t sbase = smem_u32(sm);

    float acc[2][8][4];
#pragma unroll
    for (int i = 0; i < 2; i++)
#pragma unroll
        for (int j = 0; j < 8; j++)
#pragma unroll
            for (int q = 0; q < 4; q++) acc[i][j][q] = 0.0f;

    auto load_stage = [&](int st, int kc) {
        uint32_t sa = sbase + st * STG;
        uint32_t sb = sa + A_STG;
        int ko = kc * 32;
        // A: 256 rows x 4 chunks = 1024 -> 2/thread
#pragma unroll
        for (int i = 0; i < 2; i++) {
            int idx = i * 512 + tid;
            int row = idx >> 2, c = idx & 3;
            cp16(sa + row * AROW_B + c * 16,
                 g_x + (size_t)(m0 + row) * KP + ko + c * 8);
        }
        // B: 128 rows x (4 hi + 4 lo) = 1024 -> 2/thread
#pragma unroll
        for (int i = 0; i < 2; i++) {
            int idx = i * 512 + tid;
            int row = idx >> 3, c = idx & 7;
            uint32_t dst = sb + row * BROW_B + ((c < 4) ? c * 16 : 64 + (c - 4) * 16);
            const __half* src = ((c < 4) ? g_wh : g_wl)
                                + (size_t)(n0 + row) * KP + ko + (c & 3) * 8;
            cp16(dst, src);
        }
        cp_commit();
    };

    load_stage(0, 0);
    load_stage(1, 1);

    int lrow = lane & 15;
    int acol = (lane >> 4) * 16;
    int b_lrow = (lane & 7) + ((lane >> 4) & 1) * 8;
    int b_lcol = ((lane >> 3) & 1) * 16;

    for (int kc = 0; kc < NKIT; kc++) {
        if (kc + 2 < NKIT) { load_stage((kc + 2) % NSTAGE, kc + 2); cp_wait<2>(); }
        else if (kc + 1 < NKIT) cp_wait<1>();
        else cp_wait<0>();
        __syncthreads();

        uint32_t sa = sbase + (kc % NSTAGE) * STG;
        uint32_t sb = sa + A_STG;

#pragma unroll
        for (int kk = 0; kk < 2; kk++) {
            int kb = kk * 32;
            uint32_t a_[2][4];
#pragma unroll
            for (int i = 0; i < 2; i++)
                ldsm4(a_[i], sa + (wm + i * 16 + lrow) * AROW_B + kb + acol);

#pragma unroll
            for (int jj = 0; jj < 4; jj++) {
                uint32_t bh[4], bl[4];
                uint32_t bbase = sb + (wn + jj * 16 + b_lrow) * BROW_B + kb + b_lcol;
                ldsm4(bh, bbase);
                ldsm4(bl, bbase + 64);
                uint32_t bhe[2] = {bh[0], bh[1]}, bho[2] = {bh[2], bh[3]};
                uint32_t ble[2] = {bl[0], bl[1]}, blo[2] = {bl[2], bl[3]};
                int je = jj * 2, jo = jj * 2 + 1;
#pragma unroll
                for (int i = 0; i < 2; i++) {
                    mma16816(acc[i][je], a_[i], bhe);
                    mma16816(acc[i][jo], a_[i], bho);
                    mma16816(acc[i][je], a_[i], ble);
                    mma16816(acc[i][jo], a_[i], blo);
                }
            }
        }
        __syncthreads();
    }

    // ---- epilogue: bias + relu -> g_feat ----
    int r2 = lane >> 2, c2 = (lane & 3) * 2;
#pragma unroll
    for (int i = 0; i < 2; i++) {
        int row0 = m0 + wm + i * 16 + r2;
#pragma unroll
        for (int j = 0; j < 8; j++) {
            int col = n0 + wn + j * 8 + c2;
            float b0 = bias[col], b1 = bias[col + 1];
            float2 v0 = {fmaxf(acc[i][j][0] + b0, 0.0f), fmaxf(acc[i][j][1] + b1, 0.0f)};
            float2 v1 = {fmaxf(acc[i][j][2] + b0, 0.0f), fmaxf(acc[i][j][3] + b1, 0.0f)};
            *(float2*)(g_feat + (size_t)row0 * CDIM + col) = v0;
            *(float2*)(g_feat + (size_t)(row0 + 8) * CDIM + col) = v1;
        }
    }
}

// ---------------- K6: LN2 + output GEMM (6 cols) + biases ----------------
__global__ __launch_bounds__(256) void out_kernel(const float* __restrict__ g2,
                                                  const float* __restrict__ b2,
                                                  const float* __restrict__ out_w,
                                                  const float* __restrict__ out_b,
                                                  float* __restrict__ out) {
    __shared__ float sw[6 * CDIM];
    for (int i = threadIdx.x; i < 6 * CDIM; i += 256) sw[i] = out_w[i];
    __syncthreads();

    int warp = threadIdx.x >> 5;
    int lane = threadIdx.x & 31;
    int row = blockIdx.x * 8 + warp;

    const float* f = g_feat + (size_t)row * CDIM;
    float v[32];
    float s = 0.0f;
#pragma unroll
    for (int k = 0; k < 32; k++) { v[k] = f[k * 32 + lane]; s += v[k]; }
    s = warp_sum(s);
    float mu = s * (1.0f / CDIM);
    float sq = 0.0f;
#pragma unroll
    for (int k = 0; k < 32; k++) { float d = v[k] - mu; sq += d * d; }
    sq = warp_sum(sq);
    float rs = rsqrtf(sq * (1.0f / CDIM) + EPS);

    float acc[6] = {0, 0, 0, 0, 0, 0};
#pragma unroll
    for (int k = 0; k < 32; k++) {
        int j = k * 32 + lane;
        float y = g2[j] * (v[k] - mu) * rs + b2[j];
#pragma unroll
        for (int c = 0; c < 6; c++) acc[c] += y * sw[c * CDIM + j];
    }
#pragma unroll
    for (int c = 0; c < 6; c++) acc[c] = warp_sum(acc[c]);

    if (lane == 0) {
#pragma unroll
        for (int c = 0; c < 6; c++)
            out[row * 6 + c] = acc[c] + out_b[c] + g_bias6[row * 6 + c];
    }
}

// ---------------- launch ----------------
extern "C" void kernel_launch(void* const* d_in, const int* in_sizes, int n_in,
                              void* d_out, int out_size) {
    const float* encode     = (const float*)d_in[0];
    const float* credit_vec = (const float*)d_in[1];
    const float* meta_table = (const float*)d_in[2];
    const float* conv_w     = (const float*)d_in[3];
    const float* conv_b     = (const float*)d_in[4];
    const float* ln1_g      = (const float*)d_in[5];
    const float* ln1_b      = (const float*)d_in[6];
    const float* mlp1_w     = (const float*)d_in[7];
    const float* mlp1_b     = (const float*)d_in[8];
    const float* ln2_g      = (const float*)d_in[9];
    const float* ln2_b      = (const float*)d_in[10];
    const float* out_w      = (const float*)d_in[11];
    const float* out_b      = (const float*)d_in[12];
    const int*   meta_ids   = (const int*)d_in[13];
    const int*   cat_ids    = (const int*)d_in[14];
    const int*   cat_seg    = (const int*)d_in[15];
    float* out = (float*)d_out;

    static bool init = false;
    if (!init) {
        cudaFuncSetAttribute(gemm1_mma, cudaFuncAttributeMaxDynamicSharedMemorySize, SMEM_TOT);
        init = true;
    }

    zero_kernel<<<(BATCH * MD + 255) / 256, 256>>>();
    seg_kernel<<<(NCAT + 255) / 256, 256>>>(meta_table, cat_ids, cat_seg);
    meta_kernel<<<(BATCH + 127) / 128, 128>>>(meta_table, conv_w, conv_b, meta_ids, credit_vec);
    ln1_kernel<<<BATCH / 8, 256>>>(encode, ln1_g, ln1_b);
    wconv_kernel<<<(CDIM * KP + 255) / 256, 256>>>(mlp1_w);
    {
        dim3 grid(CDIM / B_ROWS, BATCH / A_ROWS);   // (8, 128), N fastest
        gemm1_mma<<<grid, 512, SMEM_TOT>>>(mlp1_b);
    }
    out_kernel<<<BATCH / 8, 256>>>(ln2_g, ln2_b, out_w, out_b, out);
}

// round 7
// speedup vs baseline: 4.5420x; 1.2931x over previous
#include <cuda_runtime.h>
#include <cuda_fp16.h>
#include <cstdint>

#define BATCH 32768
#define HDIM  512
#define MD    8
#define CDIM  1024
#define NCAT  262144
#define KDIM  532
#define KP    544            // K padded to 17*32
#define NKIT  17
#define EPS   1e-6f

// ---------------- static scratch ----------------
__device__ float g_sums[BATCH * MD];
__device__ float g_counts[BATCH];
__device__ float g_meta[BATCH * 20];
__device__ float g_bias6[BATCH * 6];
__device__ __half g_x[(size_t)BATCH * KP];     // 35.7 MB
__device__ __half g_w[CDIM * KP];              // 1.1 MB
__device__ __half g_feat[(size_t)BATCH * CDIM];// 64 MB (fp16 now)

// ---------------- helpers ----------------
__device__ __forceinline__ float warp_sum(float v) {
#pragma unroll
    for (int o = 16; o > 0; o >>= 1) v += __shfl_xor_sync(0xffffffffu, v, o);
    return v;
}
__device__ __forceinline__ uint32_t smem_u32(const void* p) {
    uint32_t a;
    asm("{ .reg .u64 t; cvta.to.shared.u64 t, %1; cvt.u32.u64 %0, t; }" : "=r"(a) : "l"(p));
    return a;
}
__device__ __forceinline__ void cp16(uint32_t dst, const void* src) {
    unsigned long long g = (unsigned long long)__cvta_generic_to_global(src);
    asm volatile("cp.async.cg.shared.global [%0], [%1], 16;" :: "r"(dst), "l"(g) : "memory");
}
__device__ __forceinline__ void cp_commit() {
    asm volatile("cp.async.commit_group;" ::: "memory");
}
template <int N>
__device__ __forceinline__ void cp_wait() {
    asm volatile("cp.async.wait_group %0;" :: "n"(N) : "memory");
}
__device__ __forceinline__ void ldsm4(uint32_t* r, uint32_t addr) {
    asm volatile("ldmatrix.sync.aligned.m8n8.x4.shared.b16 {%0,%1,%2,%3}, [%4];"
                 : "=r"(r[0]), "=r"(r[1]), "=r"(r[2]), "=r"(r[3]) : "r"(addr));
}
__device__ __forceinline__ void mma16816(float* d, const uint32_t* a, const uint32_t* b) {
    asm volatile(
        "mma.sync.aligned.m16n8k16.row.col.f32.f16.f16.f32 "
        "{%0,%1,%2,%3}, {%4,%5,%6,%7}, {%8,%9}, {%0,%1,%2,%3};"
        : "+f"(d[0]), "+f"(d[1]), "+f"(d[2]), "+f"(d[3])
        : "r"(a[0]), "r"(a[1]), "r"(a[2]), "r"(a[3]), "r"(b[0]), "r"(b[1]));
}

// ---------------- K0: zero segment scratch ----------------
__global__ void zero_kernel() {
    int i = blockIdx.x * blockDim.x + threadIdx.x;
    if (i < BATCH * MD) g_sums[i] = 0.0f;
    if (i < BATCH) g_counts[i] = 0.0f;
}

// ---------------- K1: ragged segment sum ----------------
__global__ void seg_kernel(const float* __restrict__ meta_table,
                           const int* __restrict__ cat_ids,
                           const int* __restrict__ cat_seg) {
    int i = blockIdx.x * blockDim.x + threadIdx.x;
    if (i >= NCAT) return;
    int c = cat_ids[i];
    int s = cat_seg[i];
    const float* e = meta_table + (size_t)c * MD;
#pragma unroll
    for (int d = 0; d < MD; d++) atomicAdd(&g_sums[s * MD + d], e[d]);
    atomicAdd(&g_counts[s], 1.0f);
}

// ---------------- K2: conv/relu/maxpool + credit biases ----------------
__global__ void meta_kernel(const float* __restrict__ meta_table,
                            const float* __restrict__ conv_w,
                            const float* __restrict__ conv_b,
                            const int* __restrict__ meta_ids,
                            const float* __restrict__ credit) {
    int b = blockIdx.x * blockDim.x + threadIdx.x;
    if (b >= BATCH) return;

    float mat[6][MD];
    float cnt = fmaxf(g_counts[b], 1.0f);
#pragma unroll
    for (int d = 0; d < MD; d++) mat[0][d] = g_sums[b * MD + d] / cnt;
#pragma unroll
    for (int r = 0; r < 5; r++) {
        int id = meta_ids[b * 5 + r];
        const float* e = meta_table + (size_t)id * MD;
#pragma unroll
        for (int d = 0; d < MD; d++) mat[r + 1][d] = e[d];
    }
    float conv[5][6];
#pragma unroll
    for (int o = 0; o < 5; o++) {
#pragma unroll
        for (int t = 0; t < 6; t++) {
            float a = conv_b[o];
#pragma unroll
            for (int i = 0; i < 6; i++)
#pragma unroll
                for (int k = 0; k < 3; k++)
                    a += mat[i][t + k] * conv_w[o * 18 + i * 3 + k];
            conv[o][t] = fmaxf(a, 0.0f);
        }
    }
#pragma unroll
    for (int o = 0; o < 5; o++)
#pragma unroll
        for (int t = 0; t < 4; t++)
            g_meta[b * 20 + o * 4 + t] =
                fmaxf(fmaxf(conv[o][t], conv[o][t + 1]), conv[o][t + 2]);

    float cv[6], s = 0.0f;
#pragma unroll
    for (int c = 0; c < 6; c++) { cv[c] = credit[b * 6 + c]; s += cv[c]; }
#pragma unroll
    for (int c = 0; c < 6; c++)
        g_bias6[b * 6 + c] = (s > 0.0f) ? cv[c] / s : (1.0f / 6.0f);
}

// ---------------- K3: LN1 -> fp16, K padded to 544 ----------------
__global__ __launch_bounds__(256) void ln1_kernel(const float* __restrict__ encode,
                                                  const float* __restrict__ g1,
                                                  const float* __restrict__ b1) {
    int warp = threadIdx.x >> 5;
    int lane = threadIdx.x & 31;
    int row = blockIdx.x * 8 + warp;

    float v[17];
#pragma unroll
    for (int k = 0; k < 17; k++) {
        int j = k * 32 + lane;
        float x = 0.0f;
        if (j < HDIM)      x = encode[(size_t)row * HDIM + j];
        else if (j < KDIM) x = g_meta[row * 20 + (j - HDIM)];
        v[k] = x;
    }
    float s = 0.0f;
#pragma unroll
    for (int k = 0; k < 17; k++) s += v[k];
    s = warp_sum(s);
    float mu = s * (1.0f / KDIM);
    float sq = 0.0f;
#pragma unroll
    for (int k = 0; k < 17; k++) {
        int j = k * 32 + lane;
        float d = (j < KDIM) ? (v[k] - mu) : 0.0f;
        sq += d * d;
    }
    sq = warp_sum(sq);
    float rs = rsqrtf(sq * (1.0f / KDIM) + EPS);

    __half* dx = g_x + (size_t)row * KP;
#pragma unroll
    for (int k = 0; k < 17; k++) {
        int j = k * 32 + lane;
        float y = (j < KDIM) ? (g1[j] * (v[k] - mu) * rs + b1[j]) : 0.0f;
        dx[j] = __float2half(y);
    }
}

// ---------------- K4: W1 -> fp16, padded ----------------
__global__ void wconv_kernel(const float* __restrict__ w) {
    int idx = blockIdx.x * blockDim.x + threadIdx.x;
    if (idx >= CDIM * KP) return;
    int n = idx / KP;
    int k = idx - n * KP;
    float v = (k < KDIM) ? w[(size_t)n * KDIM + k] : 0.0f;
    g_w[idx] = __float2half(v);
}

// ---------------- K5: fp16 1-term GEMM  feat = relu(x @ W^T + b) ----------------
// CTA 256x128, 512 threads (16 warps), warp tile 32x64, K chunk 32, 4-stage cp.async.
// Rows: 64B data + 16B pad = 80B (20-word stride, ldmatrix conflict-free).
#define A_ROWS  256
#define B_ROWS  128
#define ROW_B   80
#define A_STG   (A_ROWS * ROW_B)           // 20480
#define B_STG   (B_ROWS * ROW_B)           // 10240
#define STG     (A_STG + B_STG)            // 30720
#define NSTAGE  4
#define SMEM_TOT (NSTAGE * STG)            // 122880

__global__ __launch_bounds__(512, 1) void gemm1_mma(const float* __restrict__ bias) {
    extern __shared__ char sm[];
    int tid = threadIdx.x;
    int lane = tid & 31;
    int w = tid >> 5;
    int wm = (w & 7) * 32;      // 8 M-warps
    int wn = (w >> 3) * 64;     // 2 N-warps

    int m0 = blockIdx.y * A_ROWS;
    int n0 = blockIdx.x * B_ROWS;

    uint32_t sbase = smem_u32(sm);

    float acc[2][8][4];
#pragma unroll
    for (int i = 0; i < 2; i++)
#pragma unroll
        for (int j = 0; j < 8; j++)
#pragma unroll
            for (int q = 0; q < 4; q++) acc[i][j][q] = 0.0f;

    auto load_stage = [&](int st, int kc) {
        uint32_t sa = sbase + st * STG;
        uint32_t sb = sa + A_STG;
        int ko = kc * 32;
        // A: 256 rows x 4 chunks(16B) = 1024 -> 2/thread
#pragma unroll
        for (int i = 0; i < 2; i++) {
            int idx = i * 512 + tid;
            int row = idx >> 2, c = idx & 3;
            cp16(sa + row * ROW_B + c * 16,
                 g_x + (size_t)(m0 + row) * KP + ko + c * 8);
        }
        // B: 128 rows x 4 chunks = 512 -> 1/thread
        {
            int row = tid >> 2, c = tid & 3;
            cp16(sb + row * ROW_B + c * 16,
                 g_w + (size_t)(n0 + row) * KP + ko + c * 8);
        }
        cp_commit();
    };

    load_stage(0, 0);
    load_stage(1, 1);
    load_stage(2, 2);

    int lrow = lane & 15;
    int acol = (lane >> 4) * 16;
    int b_lrow = (lane & 7) + ((lane >> 4) & 1) * 8;
    int b_lcol = ((lane >> 3) & 1) * 16;

    for (int kc = 0; kc < NKIT; kc++) {
        if (kc + 3 < NKIT) { load_stage((kc + 3) & 3, kc + 3); cp_wait<3>(); }
        else if (kc + 2 < NKIT) cp_wait<2>();
        else if (kc + 1 < NKIT) cp_wait<1>();
        else cp_wait<0>();
        __syncthreads();

        uint32_t sa = sbase + (kc & 3) * STG;
        uint32_t sb = sa + A_STG;

#pragma unroll
        for (int kk = 0; kk < 2; kk++) {
            int kb = kk * 32;
            uint32_t a_[2][4];
#pragma unroll
            for (int i = 0; i < 2; i++)
                ldsm4(a_[i], sa + (wm + i * 16 + lrow) * ROW_B + kb + acol);

#pragma unroll
            for (int jj = 0; jj < 4; jj++) {
                uint32_t bh[4];
                ldsm4(bh, sb + (wn + jj * 16 + b_lrow) * ROW_B + kb + b_lcol);
                uint32_t be[2] = {bh[0], bh[1]}, bo[2] = {bh[2], bh[3]};
                int je = jj * 2, jo = jj * 2 + 1;
#pragma unroll
                for (int i = 0; i < 2; i++) {
                    mma16816(acc[i][je], a_[i], be);
                    mma16816(acc[i][jo], a_[i], bo);
                }
            }
        }
        __syncthreads();
    }

    // ---- epilogue: bias + relu -> g_feat (fp16) ----
    int r2 = lane >> 2, c2 = (lane & 3) * 2;
#pragma unroll
    for (int i = 0; i < 2; i++) {
        int row0 = m0 + wm + i * 16 + r2;
#pragma unroll
        for (int j = 0; j < 8; j++) {
            int col = n0 + wn + j * 8 + c2;
            float b0 = bias[col], b1 = bias[col + 1];
            __half2 v0 = __floats2half2_rn(fmaxf(acc[i][j][0] + b0, 0.0f),
                                           fmaxf(acc[i][j][1] + b1, 0.0f));
            __half2 v1 = __floats2half2_rn(fmaxf(acc[i][j][2] + b0, 0.0f),
                                           fmaxf(acc[i][j][3] + b1, 0.0f));
            *(__half2*)(g_feat + (size_t)row0 * CDIM + col) = v0;
            *(__half2*)(g_feat + (size_t)(row0 + 8) * CDIM + col) = v1;
        }
    }
}

// ---------------- K6: LN2 + output GEMM (6 cols) + biases ----------------
__global__ __launch_bounds__(256) void out_kernel(const float* __restrict__ g2,
                                                  const float* __restrict__ b2,
                                                  const float* __restrict__ out_w,
                                                  const float* __restrict__ out_b,
                                                  float* __restrict__ out) {
    __shared__ float sw[6 * CDIM];
    for (int i = threadIdx.x; i < 6 * CDIM; i += 256) sw[i] = out_w[i];
    __syncthreads();

    int warp = threadIdx.x >> 5;
    int lane = threadIdx.x & 31;
    int row = blockIdx.x * 8 + warp;

    const __half2* f = (const __half2*)(g_feat + (size_t)row * CDIM);
    // lane handles 16 half2 at positions lane + k*32 (coalesced)
    float2 v[16];
    float s = 0.0f;
#pragma unroll
    for (int k = 0; k < 16; k++) {
        v[k] = __half22float2(f[lane + k * 32]);
        s += v[k].x + v[k].y;
    }
    s = warp_sum(s);
    float mu = s * (1.0f / CDIM);
    float sq = 0.0f;
#pragma unroll
    for (int k = 0; k < 16; k++) {
        float dx = v[k].x - mu, dy = v[k].y - mu;
        sq += dx * dx + dy * dy;
    }
    sq = warp_sum(sq);
    float rs = rsqrtf(sq * (1.0f / CDIM) + EPS);

    float acc[6] = {0, 0, 0, 0, 0, 0};
#pragma unroll
    for (int k = 0; k < 16; k++) {
        int j = (lane + k * 32) * 2;
        float y0 = g2[j] * (v[k].x - mu) * rs + b2[j];
        float y1 = g2[j + 1] * (v[k].y - mu) * rs + b2[j + 1];
#pragma unroll
        for (int c = 0; c < 6; c++)
            acc[c] += y0 * sw[c * CDIM + j] + y1 * sw[c * CDIM + j + 1];
    }
#pragma unroll
    for (int c = 0; c < 6; c++) acc[c] = warp_sum(acc[c]);

    if (lane == 0) {
#pragma unroll
        for (int c = 0; c < 6; c++)
            out[row * 6 + c] = acc[c] + out_b[c] + g_bias6[row * 6 + c];
    }
}

// ---------------- launch ----------------
extern "C" void kernel_launch(void* const* d_in, const int* in_sizes, int n_in,
                              void* d_out, int out_size) {
    const float* encode     = (const float*)d_in[0];
    const float* credit_vec = (const float*)d_in[1];
    const float* meta_table = (const float*)d_in[2];
    const float* conv_w     = (const float*)d_in[3];
    const float* conv_b     = (const float*)d_in[4];
    const float* ln1_g      = (const float*)d_in[5];
    const float* ln1_b      = (const float*)d_in[6];
    const float* mlp1_w     = (const float*)d_in[7];
    const float* mlp1_b     = (const float*)d_in[8];
    const float* ln2_g      = (const float*)d_in[9];
    const float* ln2_b      = (const float*)d_in[10];
    const float* out_w      = (const float*)d_in[11];
    const float* out_b      = (const float*)d_in[12];
    const int*   meta_ids   = (const int*)d_in[13];
    const int*   cat_ids    = (const int*)d_in[14];
    const int*   cat_seg    = (const int*)d_in[15];
    float* out = (float*)d_out;

    static bool init = false;
    if (!init) {
        cudaFuncSetAttribute(gemm1_mma, cudaFuncAttributeMaxDynamicSharedMemorySize, SMEM_TOT);
        init = true;
    }

    zero_kernel<<<(BATCH * MD + 255) / 256, 256>>>();
    seg_kernel<<<(NCAT + 255) / 256, 256>>>(meta_table, cat_ids, cat_seg);
    meta_kernel<<<(BATCH + 127) / 128, 128>>>(meta_table, conv_w, conv_b, meta_ids, credit_vec);
    ln1_kernel<<<BATCH / 8, 256>>>(encode, ln1_g, ln1_b);
    wconv_kernel<<<(CDIM * KP + 255) / 256, 256>>>(mlp1_w);
    {
        dim3 grid(CDIM / B_ROWS, BATCH / A_ROWS);   // (8, 128), N fastest
        gemm1_mma<<<grid, 512, SMEM_TOT>>>(mlp1_b);
    }
    out_kernel<<<BATCH / 8, 256>>>(ln2_g, ln2_b, out_w, out_b, out);
}